// round 1
// baseline (speedup 1.0000x reference)
#include <cuda_runtime.h>
#include <float.h>

// Problem constants
#define N_ROWS 65536      // 64 * 1024 rows
#define D      64         // feature dim
#define K      1024       // codebook size
#define RPB    64         // rows per block
#define KT     128        // codes per smem tile
#define NKT    (K / KT)   // 8 tiles
#define TB     256        // threads per block
#define XS     68         // Xs padded row stride (floats) -> reduces transpose-store conflicts
#define ES     128        // Es row stride (floats)

// Output layout (float32): quantized | loss | indices
#define OUT_Q    0
#define OUT_LOSS (N_ROWS * D)            // 4194304
#define OUT_IDX  (N_ROWS * D + 1)        // 4194305

// smem layout (floats):
//   Xs:    D*XS   = 4352
//   Es:    D*ES   = 8192
//   en:    KT     = 128
//   xnorm: RPB    = 64
//   redv:  RPB*16 = 1024
//   redi:  RPB*16 = 1024 (ints)
//   bidx:  RPB    = 64   (ints)
//   minv:  RPB    = 64
#define SMEM_FLOATS (D*XS + D*ES + KT + RPB + RPB*16 + RPB*16 + RPB + RPB)
#define SMEM_BYTES  (SMEM_FLOATS * 4)

__device__ float g_enorm[K];
__device__ float g_partial[N_ROWS / RPB];   // 1024 per-block loss partials

// ---------------------------------------------------------------------------
// ||e_c||^2 for each code (deterministic fixed-order sums)
// ---------------------------------------------------------------------------
__global__ void enorm_kernel(const float* __restrict__ E) {
    int c = blockIdx.x * blockDim.x + threadIdx.x;
    if (c < K) {
        const float4* p = (const float4*)(E + (size_t)c * D);
        float s = 0.f;
#pragma unroll
        for (int i = 0; i < D / 4; i++) {
            float4 v = p[i];
            s = fmaf(v.x, v.x, s);
            s = fmaf(v.y, v.y, s);
            s = fmaf(v.z, v.z, s);
            s = fmaf(v.w, v.w, s);
        }
        g_enorm[c] = s;
    }
}

// ---------------------------------------------------------------------------
// Main kernel: per block of 64 rows, scan all 1024 codes.
// score(c) = ||e_c||^2 - 2 x.e_c   (||x||^2 constant for argmin, added for loss)
// Each thread: 4 rows x 8 codes microtile, acc over D.
// ---------------------------------------------------------------------------
__global__ void vq_main_kernel(const float* __restrict__ X,
                               const float* __restrict__ E,
                               float* __restrict__ out) {
    extern __shared__ float smem[];
    float* Xs    = smem;                       // [D][XS] transposed X tile
    float* Es    = Xs + D * XS;                // [D][ES] transposed E tile
    float* en    = Es + D * ES;                // [KT]
    float* xnorm = en + KT;                    // [RPB]
    float* redv  = xnorm + RPB;                // [RPB][16]
    int*   redi  = (int*)(redv + RPB * 16);    // [RPB][16]
    int*   bidx  = redi + RPB * 16;            // [RPB]
    float* minv  = (float*)(bidx + RPB);       // [RPB]

    const int tid     = threadIdx.x;
    const int rowBase = blockIdx.x * RPB;

    // Load X tile (coalesced global), store transposed [d][row] (padded stride)
#pragma unroll
    for (int i = 0; i < 4; i++) {
        int idx = tid + i * TB;     // 0..1023 float4s
        int r   = idx >> 4;         // 0..63
        int c   = idx & 15;         // 0..15 d-chunks
        float4 v = *(const float4*)(X + (size_t)(rowBase + r) * D + c * 4);
        Xs[(c * 4 + 0) * XS + r] = v.x;
        Xs[(c * 4 + 1) * XS + r] = v.y;
        Xs[(c * 4 + 2) * XS + r] = v.z;
        Xs[(c * 4 + 3) * XS + r] = v.w;
    }
    __syncthreads();

    // ||x||^2 per row (for the loss)
    if (tid < RPB) {
        float s = 0.f;
#pragma unroll
        for (int d = 0; d < D; d++) {
            float v = Xs[d * XS + tid];
            s = fmaf(v, v, s);
        }
        xnorm[tid] = s;
    }

    const int ty = tid >> 4;    // row group: rows ty*4 .. ty*4+3
    const int tx = tid & 15;    // code group: codes tx*4..+3 and 64+tx*4..+3

    float bestv[4];
    int   besti[4];
#pragma unroll
    for (int i = 0; i < 4; i++) { bestv[i] = FLT_MAX; besti[i] = 0; }

    for (int kt = 0; kt < NKT; kt++) {
        __syncthreads();   // protect Es/en reuse across iterations
        // Load E tile: lanes take consecutive codes (strided global reads hit
        // L2-resident E; smem stores are conflict-free consecutive words).
#pragma unroll
        for (int i = 0; i < 8; i++) {
            int idx  = tid + i * TB;   // 0..2047 float4s
            int code = idx & 127;
            int c    = idx >> 7;       // 0..15 d-chunks
            float4 v = *(const float4*)(E + (size_t)(kt * KT + code) * D + c * 4);
            Es[(c * 4 + 0) * ES + code] = v.x;
            Es[(c * 4 + 1) * ES + code] = v.y;
            Es[(c * 4 + 2) * ES + code] = v.z;
            Es[(c * 4 + 3) * ES + code] = v.w;
        }
        if (tid < KT) en[tid] = g_enorm[kt * KT + tid];
        __syncthreads();

        float acc[4][8];
#pragma unroll
        for (int i = 0; i < 4; i++)
#pragma unroll
            for (int j = 0; j < 8; j++) acc[i][j] = 0.f;

#pragma unroll 16
        for (int d = 0; d < D; d++) {
            float4 x4 = *(const float4*)(Xs + d * XS + ty * 4);
            float4 e0 = *(const float4*)(Es + d * ES + tx * 4);
            float4 e1 = *(const float4*)(Es + d * ES + 64 + tx * 4);
            float xv[4] = {x4.x, x4.y, x4.z, x4.w};
            float ev[8] = {e0.x, e0.y, e0.z, e0.w, e1.x, e1.y, e1.z, e1.w};
#pragma unroll
            for (int i = 0; i < 4; i++)
#pragma unroll
                for (int j = 0; j < 8; j++)
                    acc[i][j] = fmaf(xv[i], ev[j], acc[i][j]);
        }

        // score + running argmin (codes visited in increasing index per thread)
#pragma unroll
        for (int j = 0; j < 8; j++) {
            int lc = (j < 4) ? (tx * 4 + j) : (64 + tx * 4 + (j - 4));
            float e2   = en[lc];
            int  gcode = kt * KT + lc;
#pragma unroll
            for (int i = 0; i < 4; i++) {
                float s = fmaf(-2.f, acc[i][j], e2);
                if (s < bestv[i]) { bestv[i] = s; besti[i] = gcode; }
            }
        }
    }

    // Cross-thread (16 code-groups per row) argmin reduction
#pragma unroll
    for (int i = 0; i < 4; i++) {
        redv[(ty * 4 + i) * 16 + tx] = bestv[i];
        redi[(ty * 4 + i) * 16 + tx] = besti[i];
    }
    __syncthreads();

    if (tid < RPB) {
        float bv = redv[tid * 16 + 0];
        int   bi = redi[tid * 16 + 0];
#pragma unroll
        for (int s = 1; s < 16; s++) {
            float v  = redv[tid * 16 + s];
            int   ix = redi[tid * 16 + s];
            if (v < bv || (v == bv && ix < bi)) { bv = v; bi = ix; }
        }
        bidx[tid] = bi;
        minv[tid] = xnorm[tid] + bv;               // = min squared distance
        out[OUT_IDX + rowBase + tid] = (float)bi;  // indices as float
    }
    __syncthreads();

    // Per-block loss partial (deterministic fixed-order sum)
    if (tid == 0) {
        float s = 0.f;
        for (int r = 0; r < RPB; r++) s += minv[r];
        g_partial[blockIdx.x] = s;
    }

    // Gather winning code rows -> quantized output (quantized_st == quantized)
#pragma unroll
    for (int i = 0; i < 4; i++) {
        int idx = tid + i * TB;
        int r   = idx >> 4;
        int c   = idx & 15;
        float4 v = *(const float4*)(E + (size_t)bidx[r] * D + c * 4);
        *(float4*)(out + OUT_Q + (size_t)(rowBase + r) * D + c * 4) = v;
    }
}

// ---------------------------------------------------------------------------
// Final deterministic loss reduction: loss = 1.25 * mean((q-x)^2)
// ---------------------------------------------------------------------------
__global__ void loss_kernel(float* __restrict__ out) {
    __shared__ float sh[TB];
    int t = threadIdx.x;
    float s = 0.f;
    for (int i = t; i < N_ROWS / RPB; i += TB) s += g_partial[i];
    sh[t] = s;
    __syncthreads();
    for (int off = TB / 2; off > 0; off >>= 1) {
        if (t < off) sh[t] += sh[t + off];
        __syncthreads();
    }
    if (t == 0) out[OUT_LOSS] = sh[0] * (1.25f / (float)(N_ROWS * D));
}

// ---------------------------------------------------------------------------
extern "C" void kernel_launch(void* const* d_in, const int* in_sizes, int n_in,
                              void* d_out, int out_size) {
    const float* X = (const float*)d_in[0];
    const float* E = (const float*)d_in[1];
    // Robustness: if input order is swapped (embeddings first), fix it by size.
    if (n_in >= 2 && in_sizes[0] == K * D && in_sizes[1] == N_ROWS * D) {
        const float* t = X; X = E; E = t;
    }
    float* out = (float*)d_out;

    cudaFuncSetAttribute(vq_main_kernel,
                         cudaFuncAttributeMaxDynamicSharedMemorySize, SMEM_BYTES);

    enorm_kernel<<<(K + 255) / 256, 256>>>(E);
    vq_main_kernel<<<N_ROWS / RPB, TB, SMEM_BYTES>>>(X, E, out);
    loss_kernel<<<1, TB>>>(out);
}